// round 13
// baseline (speedup 1.0000x reference)
#include <cuda_runtime.h>
#include <math.h>

#define EMAX 1280
#define NMAX 384
#define FT   640      // fused threads: 2 edges each; nodes on first 384
#define MAXD 32       // padded adjacency (P(deg>32) negligible at E/N=3.3)

// ---------------- persistent device scratch ----------------------------------
__device__ int    g_snd[EMAX];
__device__ int    g_rcv[EMAX];
__device__ __align__(16) float g_h [NMAX * 8];   // [h0,h1,x0,x1,x2,0,0,0]
__device__ __align__(16) float g_ts[NMAX * 8];   // sender   [c0,c1,s1,c2,s2,c3,c4,s4]
__device__ __align__(16) float g_tr[NMAX * 8];   // receiver [c5,c6,c7,s7,c8,c9,s9,0]
__device__ float2 g_z1314[NMAX];
__device__ float2 g_ecs[9];
__device__ float2 g_ncs[11];
__device__ unsigned g_ci[NMAX], g_co[NMAX];          // degree counters (prep zeroes)
__device__ unsigned g_inl[NMAX * MAXD];              // k | (snd << 16)
__device__ unsigned g_outl[NMAX * MAXD];             // k | (rcv << 16)

// ---------------- helpers -----------------------------------------------------
__device__ __forceinline__ void rot(float& z, float& x, float ct, float st) {
    float zn = z * ct - x * st;
    x = x * ct + z * st;
    z = zn;
}

// ---------------- prep (wide): extract, H0, tables, constants ----------------
__global__ void prep_kernel(const float* __restrict__ X, const float* __restrict__ Ri,
                            const float* __restrict__ Ro, const float* __restrict__ W,
                            const float* __restrict__ te, const float* __restrict__ tn,
                            int N, int E) {
    int t = blockIdx.x * blockDim.x + threadIdx.x;
    int quarter = (N * E) >> 2;
    if (t < quarter) {
        float4 v = ((const float4*)Ro)[t];
        int base = t * 4;
        if (v.x > 0.5f) g_snd[ base      % E] =  base      / E;
        if (v.y > 0.5f) g_snd[(base + 1) % E] = (base + 1) / E;
        if (v.z > 0.5f) g_snd[(base + 2) % E] = (base + 2) / E;
        if (v.w > 0.5f) g_snd[(base + 3) % E] = (base + 3) / E;
    } else if (t < 2 * quarter) {
        int u = t - quarter;
        float4 v = ((const float4*)Ri)[u];
        int base = u * 4;
        if (v.x > 0.5f) g_rcv[ base      % E] =  base      / E;
        if (v.y > 0.5f) g_rcv[(base + 1) % E] = (base + 1) / E;
        if (v.z > 0.5f) g_rcv[(base + 2) % E] = (base + 2) / E;
        if (v.w > 0.5f) g_rcv[(base + 3) % E] = (base + 3) / E;
    }
    if (t < N) { g_ci[t] = 0u; g_co[t] = 0u; }
    if (t < N) {
        float x0 = X[t * 3 + 0], x1 = X[t * 3 + 1], x2 = X[t * 3 + 2];
        float z0 = x0 * W[0] + x1 * W[2] + x2 * W[4];
        float z1 = x0 * W[1] + x1 * W[3] + x2 * W[5];
        const float TWOPI = 6.283185307179586f;
        float hv[5];
        hv[0] = TWOPI / (1.f + __expf(-z0));
        hv[1] = TWOPI / (1.f + __expf(-z1));
        hv[2] = x0; hv[3] = x1; hv[4] = x2;
#pragma unroll
        for (int j = 0; j < 5; j++) g_h[t * 8 + j] = hv[j];
        g_h[t * 8 + 5] = 0.f; g_h[t * 8 + 6] = 0.f; g_h[t * 8 + 7] = 0.f;
        float c[5], s[5];
#pragma unroll
        for (int j = 0; j < 5; j++) sincosf(hv[j] + te[j], &s[j], &c[j]);
        g_ts[t * 8 + 0] = c[0];
        g_ts[t * 8 + 1] = c[1];  g_ts[t * 8 + 2] = s[1];
        g_ts[t * 8 + 3] = c[2];  g_ts[t * 8 + 4] = s[2];
        g_ts[t * 8 + 5] = c[3];
        g_ts[t * 8 + 6] = c[4];  g_ts[t * 8 + 7] = s[4];
#pragma unroll
        for (int j = 0; j < 5; j++) sincosf(hv[j] + te[5 + j], &s[j], &c[j]);
        g_tr[t * 8 + 0] = c[0];
        g_tr[t * 8 + 1] = c[1];
        g_tr[t * 8 + 2] = c[2];  g_tr[t * 8 + 3] = s[2];
        g_tr[t * 8 + 4] = c[3];
        g_tr[t * 8 + 5] = c[4];  g_tr[t * 8 + 6] = s[4];
        g_tr[t * 8 + 7] = 0.f;
        g_z1314[t] = make_float2(cosf(x1 + tn[13] + tn[18] + tn[22]),
                                 cosf(x2 + tn[14] + tn[19] + tn[28]));
    }
    if (t >= 3072 && t < 3081) {
        int i = t - 3072;
        float ss, cc; sincosf(te[10 + i], &ss, &cc);
        g_ecs[i] = make_float2(cc, ss);
    }
    if (t >= 3104 && t < 3115) {
        int i = t - 3104; float ang = 0.f;
        switch (i) {
            case 0:  ang = tn[16]; break;
            case 1:  ang = tn[19]; break;
            case 2:  ang = tn[14]; break;
            case 3:  ang = tn[15]; break;
            case 4:  ang = tn[20]; break;
            case 5:  ang = tn[23] + tn[26]; break;
            case 6:  ang = tn[29]; break;
            case 7:  ang = 0.5f * tn[25]; break;
            case 8:  ang = tn[17] + tn[21]; break;
            case 9:  ang = tn[24] + tn[27]; break;
            case 10: ang = tn[30]; break;
        }
        float ss, cc; sincosf(ang, &ss, &cc);
        g_ncs[i] = make_float2(cc, ss);
    }
}

// ---------------- fused single-CTA kernel: shared state, CSR gather ----------
__global__ void __launch_bounds__(FT) gnn_fused(
    const float* __restrict__ te, const float* __restrict__ tn,
    float* __restrict__ out, int N, int E) {
    __shared__ float s_ts[NMAX * 9];     // stride 9: conflict-spread
    __shared__ float s_tr[NMAX * 9];
    __shared__ float s_h [NMAX * 5];
    __shared__ float s_e [EMAX];
    int t = threadIdx.x;

    // ---- staging: tables -> shared (stride 8 -> 9), adjacency -> global lists
    for (int i = t; i < NMAX * 8; i += FT) {
        int n = i >> 3, j = i & 7;
        s_ts[n * 9 + j] = g_ts[i];
        s_tr[n * 9 + j] = g_tr[i];
        if (j < 5) s_h[n * 5 + j] = g_h[i];
    }
    int e0 = t, e1 = t + FT;
    int sn0 = g_snd[e0], rc0 = g_rcv[e0];
    int sn1 = g_snd[e1], rc1 = g_rcv[e1];
    {   // build padded adjacency lists (counters zeroed by prep each replay)
        unsigned s;
        s = atomicAdd(&g_ci[rc0], 1u); if (s < MAXD) g_inl [rc0 * MAXD + s] = (unsigned)e0 | ((unsigned)sn0 << 16);
        s = atomicAdd(&g_co[sn0], 1u); if (s < MAXD) g_outl[sn0 * MAXD + s] = (unsigned)e0 | ((unsigned)rc0 << 16);
        s = atomicAdd(&g_ci[rc1], 1u); if (s < MAXD) g_inl [rc1 * MAXD + s] = (unsigned)e1 | ((unsigned)sn1 << 16);
        s = atomicAdd(&g_co[sn1], 1u); if (s < MAXD) g_outl[sn1 * MAXD + s] = (unsigned)e1 | ((unsigned)rc1 << 16);
    }

    float2 T[9];
#pragma unroll
    for (int j = 0; j < 9; j++) T[j] = g_ecs[j];

    bool hasNode = t < N;
    float h0 = 0.f, h1 = 0.f, zc13 = 0.f, zc14 = 0.f;
    float te0 = 0.f, te1 = 0.f, te5 = 0.f, te6 = 0.f;
    float2 NC[11];
    float tn0 = 0, tn1 = 0, tn2 = 0, tn3 = 0, tn4 = 0, tn5 = 0, tn6 = 0, tn7 = 0,
          tn10 = 0, tn11 = 0, t15h = 0;
    if (hasNode) {
        h0 = g_h[t * 8 + 0];
        h1 = g_h[t * 8 + 1];
        float2 zz = g_z1314[t]; zc13 = zz.x; zc14 = zz.y;
        te0 = te[0]; te1 = te[1]; te5 = te[5]; te6 = te[6];
#pragma unroll
        for (int j = 0; j < 11; j++) NC[j] = g_ncs[j];
        tn0 = tn[0]; tn1 = tn[1]; tn2 = tn[2]; tn3 = tn[3]; tn4 = tn[4];
        tn5 = tn[5]; tn6 = tn[6]; tn7 = tn[7]; tn10 = tn[10]; tn11 = tn[11];
        t15h = 0.5f * tn[15];
    }
    __syncthreads();

    for (int it = 0; it < 3; it++) {
        // ================= edge phase: 2 edges/thread, shared tables ========
        auto edge_one = [&](int ek, int sn, int rc) {
            const float* ts = &s_ts[sn * 9];
            const float* tr = &s_tr[rc * 9];
            float c0 = ts[0], c1 = ts[1], s1v = ts[2], c2 = ts[3];
            float s2v = ts[4], c3 = ts[5], c4 = ts[6], s4v = ts[7];
            float c5 = tr[0], c6 = tr[1], c7 = tr[2], s7v = tr[3];
            float c8 = tr[4], c9 = tr[5], s9v = tr[6];

            float z1 = c1 * c0, x1 = s1v; rot(z1, x1, T[0].x, T[0].y);
            float z2 = c2 * c3, x2 = s2v; rot(z2, x2, T[1].x, T[1].y);
            z2 *= z1;                     rot(z2, x2, T[4].x, T[4].y);
            float z4 = c4 * c5, x4 = s4v; rot(z4, x4, T[5].x, T[5].y);
            z4 *= z2;                     rot(z4, x4, T[6].x, T[6].y);
            float z9 = c9 * c8, x9 = s9v; rot(z9, x9, T[3].x, T[3].y);
            float z7 = c7 * c6, x7 = s7v; rot(z7, x7, T[2].x, T[2].y);
            z7 *= z9;                     rot(z7, x7, T[7].x, T[7].y);
            z7 *= z4;                     rot(z7, x7, T[8].x, T[8].y);

            float e = 0.5f * (1.0f - z7);
            if (it < 2) s_e[ek] = e;
            else        out[ek] = e;
        };
        edge_one(e0, sn0, rc0);
        edge_one(e1, sn1, rc1);
        if (it == 2) break;
        __syncthreads();

        // ================= gather phase (reads H^t) =========================
        float f0 = 0.f, f1 = 0.f, f2 = 0.f, f3 = 0.f, f4 = 0.f;
        float f5 = 0.f, f6 = 0.f, f7 = 0.f;
        if (hasNode) {
            int n = t;
            int cin  = min((int)g_ci[n], MAXD);
            int cout = min((int)g_co[n], MAXD);
            for (int i = 0; i < cin; i++) {
                unsigned u = g_inl[n * MAXD + i];
                float e = s_e[u & 0xFFFFu];
                const float* hp = &s_h[(u >> 16) * 5];
                f0 += e * hp[0]; f1 += e * hp[1]; f2 += e * hp[2];
                f3 += e * hp[3]; f4 += e * hp[4];
            }
            for (int i = 0; i < cout; i++) {
                unsigned u = g_outl[n * MAXD + i];
                float e = s_e[u & 0xFFFFu];
                const float* hp = &s_h[(u >> 16) * 5];
                f5 += e * hp[0]; f6 += e * hp[1]; f7 += e * hp[2];
            }
        }
        __syncthreads();     // all gathers done before H^{t+1} overwrites s_h

        // ================= node phase: circuit + table update ===============
        if (hasNode) {
            int n = t;
            float2 R;
            // ---- component B: <Z10> ----
            float cA10, sA10; __sincosf(h0 + tn10, &sA10, &cA10);
            float z11 = __cosf(h1 + tn11);
            float zb = cA10 * z11, xb = sA10;
            R = NC[8];  rot(zb, xb, R.x, R.y);
            zb *= zc13;
            R = NC[9];  rot(zb, xb, R.x, R.y);
            zb *= zc14;
            R = NC[10]; rot(zb, xb, R.x, R.y);
            float zB = zb;

            // ---- component A: <Z5>, 2-branch dephasing of q1 ----
            float a0 = 0.5f * (f0 + tn0);
            float a1 = 0.5f * (f1 + tn1);
            float cg0, sg0; __sincosf(t15h + a1, &sg0, &cg0);
            float cd, sd;   __sincosf(t15h - a1, &sd, &cd);
            float cg1 = -sd, sg1 = cd;
            float ca0, sa0; __sincosf(a0, &sa0, &ca0);
            float2 R25 = NC[7];
            float w[2], zw[2];
            {
                float p0 = ca0 * cg0, p1 = sa0 * cg1;
                float q0 = p0 * R25.x - p1 * R25.y, q1 = p1 * R25.x + p0 * R25.y;
                w[0] = q0 * q0 + q1 * q1;  zw[0] = q0 * q0 - q1 * q1;
                p0 = ca0 * sg0;  p1 = sa0 * sg1;
                q0 = p0 * R25.x - p1 * R25.y;  q1 = p1 * R25.x + p0 * R25.y;
                w[1] = q0 * q0 + q1 * q1;  zw[1] = q0 * q0 - q1 * q1;
            }
            float cA2v, sA2v; __sincosf(f2 + tn2, &sA2v, &cA2v);
            float z3 = __cosf(f3 + tn3);
            float z2 = cA2v * z3, x2 = sA2v;
            R = NC[0]; rot(z2, x2, R.x, R.y);
            float2 R19 = NC[1];
            float z2b0 =  z2, x2b0 = x2; rot(z2b0, x2b0, R19.x, R19.y);
            float z2b1 = -z2, x2b1 = x2; rot(z2b1, x2b1, R19.x, R19.y);
            float cA6v, sA6v; __sincosf(f6 + tn6, &sA6v, &cA6v);
            float z7c = __cosf(f7 + tn7);
            float z6 = cA6v * z7c, x6 = sA6v;
            R = NC[3]; rot(z6, x6, R.x, R.y);
            float cA5v, sA5v; __sincosf(f5 + tn5, &sA5v, &cA5v);
            float z4c = __cosf(f4 + tn4);
            float z5 = cA5v * z4c, x5 = sA5v;
            R = NC[2]; rot(z5, x5, R.x, R.y);
            z5 *= z6;
            R = NC[4]; rot(z5, x5, R.x, R.y);
            float2 R2326 = NC[5], R29 = NC[6];
            float zA = 0.f;
#pragma unroll
            for (int bsel = 0; bsel < 2; bsel++) {
                float z = z5 * (bsel ? z2b1 : z2b0), x = x5;
                rot(z, x, R2326.x, R2326.y);
                float zp = z * zw[bsel], xp = x * w[bsel];
                zA += zp * R29.x - xp * R29.y;
            }

            const float PI_F = 3.14159265358979f;
            h0 = PI_F * (1.f - zA);
            h1 = PI_F * (1.f - zB);
            s_h[n * 5 + 0] = h0;
            s_h[n * 5 + 1] = h1;
            float ss, cc;
            __sincosf(h0 + te0, &ss, &cc); s_ts[n * 9 + 0] = cc;
            __sincosf(h1 + te1, &ss, &cc); s_ts[n * 9 + 1] = cc; s_ts[n * 9 + 2] = ss;
            s_tr[n * 9 + 0] = __cosf(h0 + te5);
            s_tr[n * 9 + 1] = __cosf(h1 + te6);
        }
        __syncthreads();
    }
}

// ---------------- launch (graph-capturable, 2 kernels) -----------------------
extern "C" void kernel_launch(void* const* d_in, const int* in_sizes, int n_in,
                              void* d_out, int out_size) {
    const float* X  = (const float*)d_in[0];
    const float* Ri = (const float*)d_in[1];
    const float* Ro = (const float*)d_in[2];
    const float* W  = (const float*)d_in[3];
    const float* te = (const float*)d_in[4];
    const float* tn = (const float*)d_in[5];
    int N = in_sizes[0] / 3;
    int E = in_sizes[1] / N;

    int pg = (2 * ((N * E) / 4) + 255) / 256;   // float4 scan of Ro + Ri
    prep_kernel<<<pg, 256>>>(X, Ri, Ro, W, te, tn, N, E);
    gnn_fused<<<1, FT>>>(te, tn, (float*)d_out, N, E);
}

// round 14
// speedup vs baseline: 1.2034x; 1.2034x over previous
#include <cuda_runtime.h>
#include <math.h>

#define EMAX 1280
#define NMAX 384
#define TPB  256
#define NBLK 5       // one cluster of 5 CTAs; 5*256 = 1280 = one thread per edge

// ---------------- persistent device scratch ----------------------------------
__device__ int    g_snd[EMAX];
__device__ int    g_rcv[EMAX];
__device__ __align__(16) float g_h [NMAX * 8];   // [h0,h1,x0,x1,x2,0,0,0]
__device__ __align__(16) float g_ts[NMAX * 8];   // sender   [c0,c1,s1,c2,s2,c3,c4,s4]
__device__ __align__(16) float g_tr[NMAX * 8];   // receiver [c5,c6,c7,s7,c8,c9,s9,0]
__device__ __align__(16) float g_mi[2][NMAX * 8];
__device__ __align__(16) float g_mo[2][NMAX * 8];
__device__ float2 g_z1314[NMAX];
__device__ float2 g_ecs[9];
__device__ float2 g_ncs[11];

// ---------------- helpers -----------------------------------------------------
__device__ __forceinline__ void rot(float& z, float& x, float ct, float st) {
    float zn = z * ct - x * st;
    x = x * ct + z * st;
    z = zn;
}

// cluster-wide barrier: HW co-scheduled, ~380 cyc (vs ~2K for L2 atomic bar)
__device__ __forceinline__ void cluster_bar() {
    __threadfence();    // publish global writes (atomics/stores) before arrive
    asm volatile("barrier.cluster.arrive.aligned;" ::: "memory");
    asm volatile("barrier.cluster.wait.aligned;" ::: "memory");
}

// ---------------- prep (wide): extract, H0, tables, constants ----------------
__global__ void prep_kernel(const float* __restrict__ X, const float* __restrict__ Ri,
                            const float* __restrict__ Ro, const float* __restrict__ W,
                            const float* __restrict__ te, const float* __restrict__ tn,
                            int N, int E) {
    int t = blockIdx.x * blockDim.x + threadIdx.x;
    int quarter = (N * E) >> 2;
    if (t < quarter) {
        float4 v = ((const float4*)Ro)[t];
        int base = t * 4;
        if (v.x > 0.5f) g_snd[ base      % E] =  base      / E;
        if (v.y > 0.5f) g_snd[(base + 1) % E] = (base + 1) / E;
        if (v.z > 0.5f) g_snd[(base + 2) % E] = (base + 2) / E;
        if (v.w > 0.5f) g_snd[(base + 3) % E] = (base + 3) / E;
    } else if (t < 2 * quarter) {
        int u = t - quarter;
        float4 v = ((const float4*)Ri)[u];
        int base = u * 4;
        if (v.x > 0.5f) g_rcv[ base      % E] =  base      / E;
        if (v.y > 0.5f) g_rcv[(base + 1) % E] = (base + 1) / E;
        if (v.z > 0.5f) g_rcv[(base + 2) % E] = (base + 2) / E;
        if (v.w > 0.5f) g_rcv[(base + 3) % E] = (base + 3) / E;
    }
    if (t < NMAX * 8) {
        g_mi[0][t] = 0.f; g_mi[1][t] = 0.f;
        g_mo[0][t] = 0.f; g_mo[1][t] = 0.f;
    }
    if (t < N) {
        float x0 = X[t * 3 + 0], x1 = X[t * 3 + 1], x2 = X[t * 3 + 2];
        float z0 = x0 * W[0] + x1 * W[2] + x2 * W[4];
        float z1 = x0 * W[1] + x1 * W[3] + x2 * W[5];
        const float TWOPI = 6.283185307179586f;
        float hv[5];
        hv[0] = TWOPI / (1.f + __expf(-z0));
        hv[1] = TWOPI / (1.f + __expf(-z1));
        hv[2] = x0; hv[3] = x1; hv[4] = x2;
#pragma unroll
        for (int j = 0; j < 5; j++) g_h[t * 8 + j] = hv[j];
        g_h[t * 8 + 5] = 0.f; g_h[t * 8 + 6] = 0.f; g_h[t * 8 + 7] = 0.f;
        float c[5], s[5];
#pragma unroll
        for (int j = 0; j < 5; j++) sincosf(hv[j] + te[j], &s[j], &c[j]);
        g_ts[t * 8 + 0] = c[0];
        g_ts[t * 8 + 1] = c[1];  g_ts[t * 8 + 2] = s[1];
        g_ts[t * 8 + 3] = c[2];  g_ts[t * 8 + 4] = s[2];
        g_ts[t * 8 + 5] = c[3];
        g_ts[t * 8 + 6] = c[4];  g_ts[t * 8 + 7] = s[4];
#pragma unroll
        for (int j = 0; j < 5; j++) sincosf(hv[j] + te[5 + j], &s[j], &c[j]);
        g_tr[t * 8 + 0] = c[0];
        g_tr[t * 8 + 1] = c[1];
        g_tr[t * 8 + 2] = c[2];  g_tr[t * 8 + 3] = s[2];
        g_tr[t * 8 + 4] = c[3];
        g_tr[t * 8 + 5] = c[4];  g_tr[t * 8 + 6] = s[4];
        g_tr[t * 8 + 7] = 0.f;
        g_z1314[t] = make_float2(cosf(x1 + tn[13] + tn[18] + tn[22]),
                                 cosf(x2 + tn[14] + tn[19] + tn[28]));
    }
    if (t >= 3072 && t < 3081) {
        int i = t - 3072;
        float ss, cc; sincosf(te[10 + i], &ss, &cc);
        g_ecs[i] = make_float2(cc, ss);
    }
    if (t >= 3104 && t < 3115) {
        int i = t - 3104; float ang = 0.f;
        switch (i) {
            case 0:  ang = tn[16]; break;
            case 1:  ang = tn[19]; break;
            case 2:  ang = tn[14]; break;
            case 3:  ang = tn[15]; break;
            case 4:  ang = tn[20]; break;
            case 5:  ang = tn[23] + tn[26]; break;
            case 6:  ang = tn[29]; break;
            case 7:  ang = 0.5f * tn[25]; break;
            case 8:  ang = tn[17] + tn[21]; break;
            case 9:  ang = tn[24] + tn[27]; break;
            case 10: ang = tn[30]; break;
        }
        float ss, cc; sincosf(ang, &ss, &cc);
        g_ncs[i] = make_float2(cc, ss);
    }
}

// ---------------- fused cluster kernel: 5 CTAs x 256, cluster barriers -------
__global__ void __launch_bounds__(TPB) __cluster_dims__(NBLK, 1, 1)
gnn_fused(const float* __restrict__ te, const float* __restrict__ tn,
          float* __restrict__ out, int N, int E) {
    int tid = blockIdx.x * TPB + threadIdx.x;    // exactly one edge per thread
    int sn = g_snd[tid], rc = g_rcv[tid];

    float2 T[9];
#pragma unroll
    for (int j = 0; j < 9; j++) T[j] = g_ecs[j];

    bool hasNode = tid < N;
    float h0 = 0.f, h1 = 0.f, zc13 = 0.f, zc14 = 0.f;
    float te0 = 0.f, te1 = 0.f, te5 = 0.f, te6 = 0.f;
    float2 NC[11];
    float tn0 = 0, tn1 = 0, tn2 = 0, tn3 = 0, tn4 = 0, tn5 = 0, tn6 = 0, tn7 = 0,
          tn10 = 0, tn11 = 0, t15h = 0;
    if (hasNode) {
        h0 = g_h[tid * 8 + 0];
        h1 = g_h[tid * 8 + 1];
        float2 zz = g_z1314[tid]; zc13 = zz.x; zc14 = zz.y;
        te0 = te[0]; te1 = te[1]; te5 = te[5]; te6 = te[6];
#pragma unroll
        for (int j = 0; j < 11; j++) NC[j] = g_ncs[j];
        tn0 = tn[0]; tn1 = tn[1]; tn2 = tn[2]; tn3 = tn[3]; tn4 = tn[4];
        tn5 = tn[5]; tn6 = tn[6]; tn7 = tn[7]; tn10 = tn[10]; tn11 = tn[11];
        t15h = 0.5f * tn[15];
    }

    for (int it = 0; it < 3; it++) {
        // ================= edge phase (table-driven, L2 data) ===============
        {
            float4 tsa = __ldcg((const float4*)&g_ts[sn * 8]);
            float4 tsb = __ldcg((const float4*)&g_ts[sn * 8 + 4]);
            float4 tra = __ldcg((const float4*)&g_tr[rc * 8]);
            float4 trb = __ldcg((const float4*)&g_tr[rc * 8 + 4]);
            float4 hs  = __ldcg((const float4*)&g_h[sn * 8]);
            float  hs4 = __ldcg(&g_h[sn * 8 + 4]);
            float4 hr  = __ldcg((const float4*)&g_h[rc * 8]);

            float c0 = tsa.x, c1 = tsa.y, s1v = tsa.z, c2 = tsa.w;
            float s2v = tsb.x, c3 = tsb.y, c4 = tsb.z, s4v = tsb.w;
            float c5 = tra.x, c6 = tra.y, c7 = tra.z, s7v = tra.w;
            float c8 = trb.x, c9 = trb.y, s9v = trb.z;

            float z1 = c1 * c0, x1 = s1v; rot(z1, x1, T[0].x, T[0].y);
            float z2 = c2 * c3, x2 = s2v; rot(z2, x2, T[1].x, T[1].y);
            z2 *= z1;                     rot(z2, x2, T[4].x, T[4].y);
            float z4 = c4 * c5, x4 = s4v; rot(z4, x4, T[5].x, T[5].y);
            z4 *= z2;                     rot(z4, x4, T[6].x, T[6].y);
            float z9 = c9 * c8, x9 = s9v; rot(z9, x9, T[3].x, T[3].y);
            float z7 = c7 * c6, x7 = s7v; rot(z7, x7, T[2].x, T[2].y);
            z7 *= z9;                     rot(z7, x7, T[7].x, T[7].y);
            z7 *= z4;                     rot(z7, x7, T[8].x, T[8].y);

            float e = 0.5f * (1.0f - z7);
            if (it < 2) {
                float* mi = g_mi[it];
                float* mo = g_mo[it];
                atomicAdd(&mi[rc * 8 + 0], e * hs.x);
                atomicAdd(&mi[rc * 8 + 1], e * hs.y);
                atomicAdd(&mi[rc * 8 + 2], e * hs.z);
                atomicAdd(&mi[rc * 8 + 3], e * hs.w);
                atomicAdd(&mi[rc * 8 + 4], e * hs4);
                // node circuit never reads mo slots 3,4 (qubits 8,9 drop out)
                atomicAdd(&mo[sn * 8 + 0], e * hr.x);
                atomicAdd(&mo[sn * 8 + 1], e * hr.y);
                atomicAdd(&mo[sn * 8 + 2], e * hr.z);
            } else {
                out[tid] = e;
            }
        }
        if (it == 2) break;
        cluster_bar();

        // ================= node phase =================
        if (hasNode) {
            int n = tid;
            float4 a  = __ldcg((const float4*)&g_mi[it][n * 8]);
            float  a4 = __ldcg(&g_mi[it][n * 8 + 4]);
            float4 bb = __ldcg((const float4*)&g_mo[it][n * 8]);
            float f0 = a.x, f1 = a.y, f2 = a.z, f3 = a.w, f4 = a4;
            float f5 = bb.x, f6 = bb.y, f7 = bb.z;

            float2 R;
            // ---- component B: <Z10> ----
            float cA10, sA10; __sincosf(h0 + tn10, &sA10, &cA10);
            float z11 = __cosf(h1 + tn11);
            float zb = cA10 * z11, xb = sA10;
            R = NC[8];  rot(zb, xb, R.x, R.y);
            zb *= zc13;
            R = NC[9];  rot(zb, xb, R.x, R.y);
            zb *= zc14;
            R = NC[10]; rot(zb, xb, R.x, R.y);
            float zB = zb;

            // ---- component A: <Z5>, 2-branch dephasing of q1 ----
            float a0 = 0.5f * (f0 + tn0);
            float a1 = 0.5f * (f1 + tn1);
            float cg0, sg0; __sincosf(t15h + a1, &sg0, &cg0);
            float cd, sd;   __sincosf(t15h - a1, &sd, &cd);
            float cg1 = -sd, sg1 = cd;
            float ca0, sa0; __sincosf(a0, &sa0, &ca0);
            float2 R25 = NC[7];
            float w[2], zw[2];
            {
                float p0 = ca0 * cg0, p1 = sa0 * cg1;
                float q0 = p0 * R25.x - p1 * R25.y, q1 = p1 * R25.x + p0 * R25.y;
                w[0] = q0 * q0 + q1 * q1;  zw[0] = q0 * q0 - q1 * q1;
                p0 = ca0 * sg0;  p1 = sa0 * sg1;
                q0 = p0 * R25.x - p1 * R25.y;  q1 = p1 * R25.x + p0 * R25.y;
                w[1] = q0 * q0 + q1 * q1;  zw[1] = q0 * q0 - q1 * q1;
            }
            float cA2v, sA2v; __sincosf(f2 + tn2, &sA2v, &cA2v);
            float z3 = __cosf(f3 + tn3);
            float z2 = cA2v * z3, x2 = sA2v;
            R = NC[0]; rot(z2, x2, R.x, R.y);
            float2 R19 = NC[1];
            float z2b0 =  z2, x2b0 = x2; rot(z2b0, x2b0, R19.x, R19.y);
            float z2b1 = -z2, x2b1 = x2; rot(z2b1, x2b1, R19.x, R19.y);
            float cA6v, sA6v; __sincosf(f6 + tn6, &sA6v, &cA6v);
            float z7c = __cosf(f7 + tn7);
            float z6 = cA6v * z7c, x6 = sA6v;
            R = NC[3]; rot(z6, x6, R.x, R.y);
            float cA5v, sA5v; __sincosf(f5 + tn5, &sA5v, &cA5v);
            float z4c = __cosf(f4 + tn4);
            float z5 = cA5v * z4c, x5 = sA5v;
            R = NC[2]; rot(z5, x5, R.x, R.y);
            z5 *= z6;
            R = NC[4]; rot(z5, x5, R.x, R.y);
            float2 R2326 = NC[5], R29 = NC[6];
            float zA = 0.f;
#pragma unroll
            for (int bsel = 0; bsel < 2; bsel++) {
                float z = z5 * (bsel ? z2b1 : z2b0), x = x5;
                rot(z, x, R2326.x, R2326.y);
                float zp = z * zw[bsel], xp = x * w[bsel];
                zA += zp * R29.x - xp * R29.y;
            }

            const float PI_F = 3.14159265358979f;
            h0 = PI_F * (1.f - zA);
            h1 = PI_F * (1.f - zB);
            g_h[n * 8 + 0] = h0;
            g_h[n * 8 + 1] = h1;
            float ss, cc;
            __sincosf(h0 + te0, &ss, &cc); g_ts[n * 8 + 0] = cc;
            __sincosf(h1 + te1, &ss, &cc); g_ts[n * 8 + 1] = cc; g_ts[n * 8 + 2] = ss;
            g_tr[n * 8 + 0] = __cosf(h0 + te5);
            g_tr[n * 8 + 1] = __cosf(h1 + te6);
        }
        cluster_bar();
    }
}

// ---------------- launch (graph-capturable, 2 kernels) -----------------------
extern "C" void kernel_launch(void* const* d_in, const int* in_sizes, int n_in,
                              void* d_out, int out_size) {
    const float* X  = (const float*)d_in[0];
    const float* Ri = (const float*)d_in[1];
    const float* Ro = (const float*)d_in[2];
    const float* W  = (const float*)d_in[3];
    const float* te = (const float*)d_in[4];
    const float* tn = (const float*)d_in[5];
    int N = in_sizes[0] / 3;
    int E = in_sizes[1] / N;

    int pg = (2 * ((N * E) / 4) + 255) / 256;   // float4 scan of Ro + Ri
    prep_kernel<<<pg, 256>>>(X, Ri, Ro, W, te, tn, N, E);
    gnn_fused<<<NBLK, TPB>>>(te, tn, (float*)d_out, N, E);
}